// round 6
// baseline (speedup 1.0000x reference)
#include <cuda_runtime.h>
#include <cuda_bf16.h>
#include <cstdint>

#define NN 200000
#define NE 640000
#define DN 128
#define DE 32
#define KTOT 288            // 128 (x) + 128 (S1) + 32 (S2)
#define NKK (KTOT / 2)      // 144 packed bf16x2 per weight row
#define NBLK1 196           // ceil(200000/1024)

// ---------------- device scratch (static: no runtime allocation) ----------------
__device__ int            g_deg[NN];
__device__ int            g_off[NN];
__device__ int            g_cursor[NN];
__device__ int            g_bsum[256];
__device__ int2           g_csr[NE];           // (edge_id, src_row) bucketed by dst
__device__ float4         g_S1[NN * 32];       // scatter-sum of x rows    [NN][128]
__device__ float4         g_S2[NN * 8];        // scatter-sum of edge_attr [NN][32]
__device__ unsigned short g_WhT[DN * KTOT];    // combined weights^T [n=128][k=288], bf16 hi
__device__ unsigned short g_WlT[DN * KTOT];    // bf16 lo residual
__device__ float          g_v[DN];             // b1 @ W2b

// ---------------- CSR build (edge_index is INT32: JAX x64 is disabled) ----------------
__global__ void k_zero_deg() {
    int i = blockIdx.x * 256 + threadIdx.x;
    if (i < NN) g_deg[i] = 0;
}

__global__ void k_count(const int* __restrict__ ei) {
    int e = blockIdx.x * 256 + threadIdx.x;
    if (e < NE) atomicAdd(&g_deg[ei[NE + e]], 1);
}

__global__ void k_scan1() {
    __shared__ int s[1024];
    int t = threadIdx.x;
    int gid = blockIdx.x * 1024 + t;
    int v = (gid < NN) ? g_deg[gid] : 0;
    s[t] = v;
    __syncthreads();
    for (int d = 1; d < 1024; d <<= 1) {
        int u = (t >= d) ? s[t - d] : 0;
        __syncthreads();
        s[t] += u;
        __syncthreads();
    }
    if (gid < NN) g_off[gid] = s[t] - v;          // exclusive within block
    if (t == 1023) g_bsum[blockIdx.x] = s[1023];  // block total
}

__global__ void k_scan2() {
    __shared__ int s[256];
    int t = threadIdx.x;
    int v = (t < NBLK1) ? g_bsum[t] : 0;
    s[t] = v;
    __syncthreads();
    for (int d = 1; d < 256; d <<= 1) {
        int u = (t >= d) ? s[t - d] : 0;
        __syncthreads();
        s[t] += u;
        __syncthreads();
    }
    if (t < NBLK1) g_bsum[t] = s[t] - v;          // exclusive block prefix
}

__global__ void k_scan3() {
    int i = blockIdx.x * 256 + threadIdx.x;
    if (i < NN) {
        int o = g_off[i] + g_bsum[i >> 10];
        g_off[i]    = o;
        g_cursor[i] = o;
    }
}

__global__ void k_scatter(const int* __restrict__ ei) {
    int e = blockIdx.x * 256 + threadIdx.x;
    if (e < NE) {
        int col = ei[NE + e];
        int row = ei[e];
        int p = atomicAdd(&g_cursor[col], 1);
        g_csr[p] = make_int2(e, row);
    }
}

// ---------------- aggregation: warp per node, no float atomics ----------------
__global__ void k_agg(const float4* __restrict__ x4, const float4* __restrict__ ea4) {
    int w    = (blockIdx.x * 256 + threadIdx.x) >> 5;
    int lane = threadIdx.x & 31;
    if (w >= NN) return;
    int start = g_off[w];
    int cnt   = g_deg[w];
    float ax = 0.f, ay = 0.f, az = 0.f, aw = 0.f;
    float ex = 0.f, ey = 0.f, ez = 0.f, ew = 0.f;
    for (int j = 0; j < cnt; j++) {
        int2 c = g_csr[start + j];
        float4 xv = x4[(long long)c.y * 32 + lane];
        ax += xv.x; ay += xv.y; az += xv.z; aw += xv.w;
        if (lane < 8) {
            float4 ev = ea4[(long long)c.x * 8 + lane];
            ex += ev.x; ey += ev.y; ez += ev.z; ew += ev.w;
        }
    }
    g_S1[(long long)w * 32 + lane] = make_float4(ax, ay, az, aw);
    if (lane < 8) g_S2[(long long)w * 8 + lane] = make_float4(ex, ey, ez, ew);
}

// ---------------- weight folding: Wc = [W2a ; W1a@W2b ; W1b@W2b], v = b1@W2b ----------------
__global__ void k_wcomb(const float* __restrict__ W1, const float* __restrict__ W2,
                        const float* __restrict__ b1) {
    int r = blockIdx.x;    // 0..288 (288 = bias-vector job)
    int j = threadIdx.x;   // 0..127
    if (r == KTOT) {
        float acc = 0.f;
        for (int k = 0; k < 128; k++) acc += b1[k] * W2[(128 + k) * 128 + j];
        g_v[j] = acc;
        return;
    }
    float w;
    if (r < 128) {
        w = W2[r * 128 + j];
    } else {
        float acc = 0.f;
        const float* w1r = W1 + (r - 128) * 128;   // rows 0..159 of W1
        for (int k = 0; k < 128; k++) acc += w1r[k] * W2[(128 + k) * 128 + j];
        w = acc;
    }
    __nv_bfloat16 hi = __float2bfloat16(w);
    __nv_bfloat16 lo = __float2bfloat16(w - __bfloat162float(hi));
    g_WhT[j * KTOT + r] = __bfloat16_as_ushort(hi);   // transposed: [n][k]
    g_WlT[j * KTOT + r] = __bfloat16_as_ushort(lo);
}

// ---------------- node GEMM: out = [x|S1|S2] @ Wc + deg*v + b2, 3x bf16-split ----------------
#define GBM 128
#define AS 12   // u32 stride; {0..7}*12 mod 32 = {0,12,24,4,16,28,8,20} -> conflict-free frags

#define MMA_BF16(d, a, bv0, bv1)                                            \
    asm volatile("mma.sync.aligned.m16n8k16.row.col.f32.bf16.bf16.f32 "     \
                 "{%0,%1,%2,%3}, {%4,%5,%6,%7}, {%8,%9}, {%0,%1,%2,%3};\n"  \
                 : "+f"(d[0]), "+f"(d[1]), "+f"(d[2]), "+f"(d[3])           \
                 : "r"(a[0]), "r"(a[1]), "r"(a[2]), "r"(a[3]),              \
                   "r"(bv0), "r"(bv1))

__device__ __forceinline__ unsigned pack_bf16x2(float a, float b) {
    __nv_bfloat162 h = __floats2bfloat162_rn(a, b);   // a -> low, b -> high
    return *reinterpret_cast<unsigned*>(&h);
}

__global__ __launch_bounds__(256) void k_gemm(const float4* __restrict__ x4,
                                              const float* __restrict__ b2,
                                              float* __restrict__ out) {
    __shared__ unsigned Ah[GBM * AS];   // A tile hi, packed bf16x2 along k
    __shared__ unsigned Al[GBM * AS];   // A tile lo
    __shared__ unsigned Bh[DN * AS];    // B tile hi (weights^T)
    __shared__ unsigned Bl[DN * AS];    // B tile lo

    int tid  = threadIdx.x;
    int lane = tid & 31;
    int warp = tid >> 5;
    int wm   = warp & 3;    // 4 warps along M (32 rows each)
    int wn   = warp >> 2;   // 2 warps along N (64 cols each)
    int n0   = blockIdx.x * GBM;

    float acc[2][8][4];
#pragma unroll
    for (int a = 0; a < 2; a++)
#pragma unroll
        for (int b = 0; b < 8; b++)
#pragma unroll
            for (int q = 0; q < 4; q++) acc[a][b][q] = 0.f;

    for (int c = 0; c < 18; c++) {     // 18 chunks of K=16 over KTOT=288
        __syncthreads();
        // A tile: 128 rows x 16 k  (source: x | S1 | S2), split to bf16 hi/lo
#pragma unroll
        for (int it = 0; it < 2; it++) {
            int i   = tid + it * 256;           // 0..511
            int row = i >> 2, f4 = i & 3;
            int n   = n0 + row;
            float4 v = make_float4(0.f, 0.f, 0.f, 0.f);
            if (n < NN) {
                if (c < 8)       v = x4[(long long)n * 32 + c * 4 + f4];
                else if (c < 16) v = g_S1[(long long)n * 32 + (c - 8) * 4 + f4];
                else             v = g_S2[(long long)n * 8 + (c - 16) * 4 + f4];
            }
            unsigned h0 = pack_bf16x2(v.x, v.y);
            unsigned h1 = pack_bf16x2(v.z, v.w);
            float rx = v.x - __bfloat162float(__ushort_as_bfloat16((unsigned short)(h0 & 0xFFFF)));
            float ry = v.y - __bfloat162float(__ushort_as_bfloat16((unsigned short)(h0 >> 16)));
            float rz = v.z - __bfloat162float(__ushort_as_bfloat16((unsigned short)(h1 & 0xFFFF)));
            float rw = v.w - __bfloat162float(__ushort_as_bfloat16((unsigned short)(h1 >> 16)));
            int base = row * AS + f4 * 2;
            Ah[base + 0] = h0;
            Ah[base + 1] = h1;
            Al[base + 0] = pack_bf16x2(rx, ry);
            Al[base + 1] = pack_bf16x2(rz, rw);
        }
        // B tile: 128 n x 16 k, straight copy of pre-split packed weights
        {
            const uint4* wh4 = reinterpret_cast<const uint4*>(g_WhT);
            const uint4* wl4 = reinterpret_cast<const uint4*>(g_WlT);
            // 128 n * 8 kk / 4-per-uint4 = 256 uint4 -> one per thread
            int n  = tid >> 1;                  // 0..127
            int q  = tid & 1;                   // 0..1 (kk quad)
            uint4 vh = wh4[n * (NKK / 4) + c * 2 + q];
            uint4 vl = wl4[n * (NKK / 4) + c * 2 + q];
            int base = n * AS + q * 4;
            Bh[base + 0] = vh.x; Bh[base + 1] = vh.y; Bh[base + 2] = vh.z; Bh[base + 3] = vh.w;
            Bl[base + 0] = vl.x; Bl[base + 1] = vl.y; Bl[base + 2] = vl.z; Bl[base + 3] = vl.w;
        }
        __syncthreads();

        unsigned ah[2][4], al[2][4];
#pragma unroll
        for (int tm = 0; tm < 2; tm++) {
            int r  = wm * 32 + tm * 16 + (lane >> 2);
            int kk = lane & 3;
            ah[tm][0] = Ah[r * AS + kk];
            ah[tm][1] = Ah[(r + 8) * AS + kk];
            ah[tm][2] = Ah[r * AS + kk + 4];
            ah[tm][3] = Ah[(r + 8) * AS + kk + 4];
            al[tm][0] = Al[r * AS + kk];
            al[tm][1] = Al[(r + 8) * AS + kk];
            al[tm][2] = Al[r * AS + kk + 4];
            al[tm][3] = Al[(r + 8) * AS + kk + 4];
        }
#pragma unroll
        for (int tn = 0; tn < 8; tn++) {
            int col = wn * 64 + tn * 8 + (lane >> 2);
            int kk  = lane & 3;
            unsigned bh0 = Bh[col * AS + kk];
            unsigned bh1 = Bh[col * AS + kk + 4];
            unsigned bl0 = Bl[col * AS + kk];
            unsigned bl1 = Bl[col * AS + kk + 4];
#pragma unroll
            for (int tm = 0; tm < 2; tm++) {
                MMA_BF16(acc[tm][tn], ah[tm], bh0, bh1);   // hi*hi
                MMA_BF16(acc[tm][tn], ah[tm], bl0, bl1);   // hi*lo
                MMA_BF16(acc[tm][tn], al[tm], bh0, bh1);   // lo*hi
            }
        }
    }
    // epilogue: + deg*v + b2
#pragma unroll
    for (int tm = 0; tm < 2; tm++) {
        int r0 = n0 + wm * 32 + tm * 16 + (lane >> 2);
        int r1 = r0 + 8;
        float d0 = (r0 < NN) ? (float)g_deg[r0] : 0.f;
        float d1 = (r1 < NN) ? (float)g_deg[r1] : 0.f;
#pragma unroll
        for (int tn = 0; tn < 8; tn++) {
            int cc = wn * 64 + tn * 8 + 2 * (lane & 3);
            float v0 = g_v[cc], v1 = g_v[cc + 1];
            float c0 = b2[cc],  c1 = b2[cc + 1];
            if (r0 < NN) {
                out[(long long)r0 * 128 + cc]     = acc[tm][tn][0] + d0 * v0 + c0;
                out[(long long)r0 * 128 + cc + 1] = acc[tm][tn][1] + d0 * v1 + c1;
            }
            if (r1 < NN) {
                out[(long long)r1 * 128 + cc]     = acc[tm][tn][2] + d1 * v0 + c0;
                out[(long long)r1 * 128 + cc + 1] = acc[tm][tn][3] + d1 * v1 + c1;
            }
        }
    }
}

// ---------------- launch ----------------
extern "C" void kernel_launch(void* const* d_in, const int* in_sizes, int n_in,
                              void* d_out, int out_size) {
    const float* x  = (const float*)d_in[0];
    const int*   ei = (const int*)d_in[1];     // int32! JAX x64 disabled
    const float* ea = (const float*)d_in[2];
    // d_in[3]=u, d_in[4]=batch: unused by the reference computation
    const float* W1 = (const float*)d_in[5];
    const float* b1 = (const float*)d_in[6];
    const float* W2 = (const float*)d_in[7];
    const float* b2 = (const float*)d_in[8];
    float*       out = (float*)d_out;

    (void)in_sizes; (void)n_in; (void)out_size;

    k_zero_deg<<<(NN + 255) / 256, 256>>>();
    k_count<<<(NE + 255) / 256, 256>>>(ei);
    k_scan1<<<NBLK1, 1024>>>();
    k_scan2<<<1, 256>>>();
    k_scan3<<<(NN + 255) / 256, 256>>>();
    k_scatter<<<(NE + 255) / 256, 256>>>(ei);
    k_agg<<<(NN + 7) / 8, 256>>>((const float4*)x, (const float4*)ea);
    k_wcomb<<<KTOT + 1, 128>>>(W1, W2, b1);
    k_gemm<<<(NN + GBM - 1) / GBM, 256>>>((const float4*)x, b2, out);
}

// round 7
// speedup vs baseline: 1.0006x; 1.0006x over previous
#include <cuda_runtime.h>
#include <cuda_bf16.h>
#include <cstdint>

#define NN 200000
#define NE 640000
#define DN 128
#define DE 32
#define KTOT 288            // 128 (x) + 128 (S1) + 32 (S2)
#define NKK (KTOT / 2)      // 144 packed bf16x2 per weight row
#define NBLK1 196           // ceil(200000/1024)

// ---------------- device scratch (static: no runtime allocation) ----------------
__device__ int            g_deg[NN];
__device__ int            g_off[NN];
__device__ int            g_cursor[NN];
__device__ int            g_bsum[256];
__device__ int2           g_csr[NE];           // (edge_id, src_row) bucketed by dst
__device__ float4         g_S1[NN * 32];       // scatter-sum of x rows    [NN][128]
__device__ float4         g_S2[NN * 8];        // scatter-sum of edge_attr [NN][32]
__device__ unsigned short g_WhT[DN * KTOT];    // combined weights^T [n=128][k=288], bf16 hi
__device__ unsigned short g_WlT[DN * KTOT];    // bf16 lo residual
__device__ float          g_v[DN];             // b1 @ W2b

// ---------------- CSR build (edge_index is INT32: JAX x64 is disabled) ----------------
__global__ void k_zero_deg() {
    int i = blockIdx.x * 256 + threadIdx.x;
    if (i < NN) g_deg[i] = 0;
}

__global__ void k_count(const int* __restrict__ ei) {
    int e = blockIdx.x * 256 + threadIdx.x;
    if (e < NE) atomicAdd(&g_deg[ei[NE + e]], 1);
}

__global__ void k_scan1() {
    __shared__ int s[1024];
    int t = threadIdx.x;
    int gid = blockIdx.x * 1024 + t;
    int v = (gid < NN) ? g_deg[gid] : 0;
    s[t] = v;
    __syncthreads();
    for (int d = 1; d < 1024; d <<= 1) {
        int u = (t >= d) ? s[t - d] : 0;
        __syncthreads();
        s[t] += u;
        __syncthreads();
    }
    if (gid < NN) g_off[gid] = s[t] - v;          // exclusive within block
    if (t == 1023) g_bsum[blockIdx.x] = s[1023];  // block total
}

__global__ void k_scan2() {
    __shared__ int s[256];
    int t = threadIdx.x;
    int v = (t < NBLK1) ? g_bsum[t] : 0;
    s[t] = v;
    __syncthreads();
    for (int d = 1; d < 256; d <<= 1) {
        int u = (t >= d) ? s[t - d] : 0;
        __syncthreads();
        s[t] += u;
        __syncthreads();
    }
    if (t < NBLK1) g_bsum[t] = s[t] - v;          // exclusive block prefix
}

__global__ void k_scan3() {
    int i = blockIdx.x * 256 + threadIdx.x;
    if (i < NN) {
        int o = g_off[i] + g_bsum[i >> 10];
        g_off[i]    = o;
        g_cursor[i] = o;
    }
}

__global__ void k_scatter(const int* __restrict__ ei) {
    int e = blockIdx.x * 256 + threadIdx.x;
    if (e < NE) {
        int col = ei[NE + e];
        int row = ei[e];
        int p = atomicAdd(&g_cursor[col], 1);
        g_csr[p] = make_int2(e, row);
    }
}

// ---------------- aggregation: warp per node, no float atomics ----------------
__global__ void k_agg(const float4* __restrict__ x4, const float4* __restrict__ ea4) {
    int w    = (blockIdx.x * 256 + threadIdx.x) >> 5;
    int lane = threadIdx.x & 31;
    if (w >= NN) return;
    int start = g_off[w];
    int cnt   = g_deg[w];
    float ax = 0.f, ay = 0.f, az = 0.f, aw = 0.f;
    float ex = 0.f, ey = 0.f, ez = 0.f, ew = 0.f;
    for (int j = 0; j < cnt; j++) {
        int2 c = g_csr[start + j];
        float4 xv = x4[(long long)c.y * 32 + lane];
        ax += xv.x; ay += xv.y; az += xv.z; aw += xv.w;
        if (lane < 8) {
            float4 ev = ea4[(long long)c.x * 8 + lane];
            ex += ev.x; ey += ev.y; ez += ev.z; ew += ev.w;
        }
    }
    g_S1[(long long)w * 32 + lane] = make_float4(ax, ay, az, aw);
    if (lane < 8) g_S2[(long long)w * 8 + lane] = make_float4(ex, ey, ez, ew);
}

// ---------------- weight folding: Wc = [W2a ; W1a@W2b ; W1b@W2b], v = b1@W2b ----------------
__global__ void k_wcomb(const float* __restrict__ W1, const float* __restrict__ W2,
                        const float* __restrict__ b1) {
    int r = blockIdx.x;    // 0..288 (288 = bias-vector job)
    int j = threadIdx.x;   // 0..127
    if (r == KTOT) {
        float acc = 0.f;
        for (int k = 0; k < 128; k++) acc += b1[k] * W2[(128 + k) * 128 + j];
        g_v[j] = acc;
        return;
    }
    float w;
    if (r < 128) {
        w = W2[r * 128 + j];
    } else {
        float acc = 0.f;
        const float* w1r = W1 + (r - 128) * 128;   // rows 0..159 of W1
        for (int k = 0; k < 128; k++) acc += w1r[k] * W2[(128 + k) * 128 + j];
        w = acc;
    }
    __nv_bfloat16 hi = __float2bfloat16(w);
    __nv_bfloat16 lo = __float2bfloat16(w - __bfloat162float(hi));
    g_WhT[j * KTOT + r] = __bfloat16_as_ushort(hi);   // transposed: [n][k]
    g_WlT[j * KTOT + r] = __bfloat16_as_ushort(lo);
}

// ---------------- node GEMM: out = [x|S1|S2] @ Wc + deg*v + b2, 3x bf16-split ----------------
#define GBM 128
#define AS 12   // u32 stride; {0..7}*12 mod 32 = {0,12,24,4,16,28,8,20} -> conflict-free frags

#define MMA_BF16(d, a, bv0, bv1)                                            \
    asm volatile("mma.sync.aligned.m16n8k16.row.col.f32.bf16.bf16.f32 "     \
                 "{%0,%1,%2,%3}, {%4,%5,%6,%7}, {%8,%9}, {%0,%1,%2,%3};\n"  \
                 : "+f"(d[0]), "+f"(d[1]), "+f"(d[2]), "+f"(d[3])           \
                 : "r"(a[0]), "r"(a[1]), "r"(a[2]), "r"(a[3]),              \
                   "r"(bv0), "r"(bv1))

__device__ __forceinline__ unsigned pack_bf16x2(float a, float b) {
    __nv_bfloat162 h = __floats2bfloat162_rn(a, b);   // a -> low, b -> high
    return *reinterpret_cast<unsigned*>(&h);
}

__global__ __launch_bounds__(256) void k_gemm(const float4* __restrict__ x4,
                                              const float* __restrict__ b2,
                                              float* __restrict__ out) {
    __shared__ unsigned Ah[GBM * AS];   // A tile hi, packed bf16x2 along k
    __shared__ unsigned Al[GBM * AS];   // A tile lo
    __shared__ unsigned Bh[DN * AS];    // B tile hi (weights^T)
    __shared__ unsigned Bl[DN * AS];    // B tile lo

    int tid  = threadIdx.x;
    int lane = tid & 31;
    int warp = tid >> 5;
    int wm   = warp & 3;    // 4 warps along M (32 rows each)
    int wn   = warp >> 2;   // 2 warps along N (64 cols each)
    int n0   = blockIdx.x * GBM;

    float acc[2][8][4];
#pragma unroll
    for (int a = 0; a < 2; a++)
#pragma unroll
        for (int b = 0; b < 8; b++)
#pragma unroll
            for (int q = 0; q < 4; q++) acc[a][b][q] = 0.f;

    for (int c = 0; c < 18; c++) {     // 18 chunks of K=16 over KTOT=288
        __syncthreads();
        // A tile: 128 rows x 16 k  (source: x | S1 | S2), split to bf16 hi/lo
#pragma unroll
        for (int it = 0; it < 2; it++) {
            int i   = tid + it * 256;           // 0..511
            int row = i >> 2, f4 = i & 3;
            int n   = n0 + row;
            float4 v = make_float4(0.f, 0.f, 0.f, 0.f);
            if (n < NN) {
                if (c < 8)       v = x4[(long long)n * 32 + c * 4 + f4];
                else if (c < 16) v = g_S1[(long long)n * 32 + (c - 8) * 4 + f4];
                else             v = g_S2[(long long)n * 8 + (c - 16) * 4 + f4];
            }
            unsigned h0 = pack_bf16x2(v.x, v.y);
            unsigned h1 = pack_bf16x2(v.z, v.w);
            float rx = v.x - __bfloat162float(__ushort_as_bfloat16((unsigned short)(h0 & 0xFFFF)));
            float ry = v.y - __bfloat162float(__ushort_as_bfloat16((unsigned short)(h0 >> 16)));
            float rz = v.z - __bfloat162float(__ushort_as_bfloat16((unsigned short)(h1 & 0xFFFF)));
            float rw = v.w - __bfloat162float(__ushort_as_bfloat16((unsigned short)(h1 >> 16)));
            int base = row * AS + f4 * 2;
            Ah[base + 0] = h0;
            Ah[base + 1] = h1;
            Al[base + 0] = pack_bf16x2(rx, ry);
            Al[base + 1] = pack_bf16x2(rz, rw);
        }
        // B tile: 128 n x 16 k, straight copy of pre-split packed weights
        {
            const uint4* wh4 = reinterpret_cast<const uint4*>(g_WhT);
            const uint4* wl4 = reinterpret_cast<const uint4*>(g_WlT);
            // 128 n * 8 kk / 4-per-uint4 = 256 uint4 -> one per thread
            int n  = tid >> 1;                  // 0..127
            int q  = tid & 1;                   // 0..1 (kk quad)
            uint4 vh = wh4[n * (NKK / 4) + c * 2 + q];
            uint4 vl = wl4[n * (NKK / 4) + c * 2 + q];
            int base = n * AS + q * 4;
            Bh[base + 0] = vh.x; Bh[base + 1] = vh.y; Bh[base + 2] = vh.z; Bh[base + 3] = vh.w;
            Bl[base + 0] = vl.x; Bl[base + 1] = vl.y; Bl[base + 2] = vl.z; Bl[base + 3] = vl.w;
        }
        __syncthreads();

        unsigned ah[2][4], al[2][4];
#pragma unroll
        for (int tm = 0; tm < 2; tm++) {
            int r  = wm * 32 + tm * 16 + (lane >> 2);
            int kk = lane & 3;
            ah[tm][0] = Ah[r * AS + kk];
            ah[tm][1] = Ah[(r + 8) * AS + kk];
            ah[tm][2] = Ah[r * AS + kk + 4];
            ah[tm][3] = Ah[(r + 8) * AS + kk + 4];
            al[tm][0] = Al[r * AS + kk];
            al[tm][1] = Al[(r + 8) * AS + kk];
            al[tm][2] = Al[r * AS + kk + 4];
            al[tm][3] = Al[(r + 8) * AS + kk + 4];
        }
#pragma unroll
        for (int tn = 0; tn < 8; tn++) {
            int col = wn * 64 + tn * 8 + (lane >> 2);
            int kk  = lane & 3;
            unsigned bh0 = Bh[col * AS + kk];
            unsigned bh1 = Bh[col * AS + kk + 4];
            unsigned bl0 = Bl[col * AS + kk];
            unsigned bl1 = Bl[col * AS + kk + 4];
#pragma unroll
            for (int tm = 0; tm < 2; tm++) {
                MMA_BF16(acc[tm][tn], ah[tm], bh0, bh1);   // hi*hi
                MMA_BF16(acc[tm][tn], ah[tm], bl0, bl1);   // hi*lo
                MMA_BF16(acc[tm][tn], al[tm], bh0, bh1);   // lo*hi
            }
        }
    }
    // epilogue: + deg*v + b2
#pragma unroll
    for (int tm = 0; tm < 2; tm++) {
        int r0 = n0 + wm * 32 + tm * 16 + (lane >> 2);
        int r1 = r0 + 8;
        float d0 = (r0 < NN) ? (float)g_deg[r0] : 0.f;
        float d1 = (r1 < NN) ? (float)g_deg[r1] : 0.f;
#pragma unroll
        for (int tn = 0; tn < 8; tn++) {
            int cc = wn * 64 + tn * 8 + 2 * (lane & 3);
            float v0 = g_v[cc], v1 = g_v[cc + 1];
            float c0 = b2[cc],  c1 = b2[cc + 1];
            if (r0 < NN) {
                out[(long long)r0 * 128 + cc]     = acc[tm][tn][0] + d0 * v0 + c0;
                out[(long long)r0 * 128 + cc + 1] = acc[tm][tn][1] + d0 * v1 + c1;
            }
            if (r1 < NN) {
                out[(long long)r1 * 128 + cc]     = acc[tm][tn][2] + d1 * v0 + c0;
                out[(long long)r1 * 128 + cc + 1] = acc[tm][tn][3] + d1 * v1 + c1;
            }
        }
    }
}

// ---------------- launch ----------------
extern "C" void kernel_launch(void* const* d_in, const int* in_sizes, int n_in,
                              void* d_out, int out_size) {
    const float* x  = (const float*)d_in[0];
    const int*   ei = (const int*)d_in[1];     // int32! JAX x64 disabled
    const float* ea = (const float*)d_in[2];
    // d_in[3]=u, d_in[4]=batch: unused by the reference computation
    const float* W1 = (const float*)d_in[5];
    const float* b1 = (const float*)d_in[6];
    const float* W2 = (const float*)d_in[7];
    const float* b2 = (const float*)d_in[8];
    float*       out = (float*)d_out;

    (void)in_sizes; (void)n_in; (void)out_size;

    k_zero_deg<<<(NN + 255) / 256, 256>>>();
    k_count<<<(NE + 255) / 256, 256>>>(ei);
    k_scan1<<<NBLK1, 1024>>>();
    k_scan2<<<1, 256>>>();
    k_scan3<<<(NN + 255) / 256, 256>>>();
    k_scatter<<<(NE + 255) / 256, 256>>>(ei);
    k_agg<<<(NN + 7) / 8, 256>>>((const float4*)x, (const float4*)ea);
    k_wcomb<<<KTOT + 1, 128>>>(W1, W2, b1);
    k_gemm<<<(NN + GBM - 1) / GBM, 256>>>((const float4*)x, b2, out);
}

// round 10
// speedup vs baseline: 1.0411x; 1.0405x over previous
#include <cuda_runtime.h>
#include <cuda_bf16.h>
#include <cstdint>

#define NN 200000
#define NE 640000
#define DN 128
#define DE 32
#define KTOT 288            // 128 (x) + 128 (S1) + 32 (S2)
#define NKK (KTOT / 2)      // 144 packed bf16x2 per weight row
#define NBLK1 196           // ceil(200000/1024)
#define GBM 64              // nodes per block; 200000 = 3125 * 64 exactly
#define NGRID 3125
#define WCOMB_BLKS (KTOT + 1)                    // 289
#define ZERO_BLKS  ((NN + 255) / 256)            // 782

// ---------------- device scratch (static: no runtime allocation) ----------------
__device__ int            g_deg[NN];
__device__ int            g_off[NN];
__device__ int            g_cursor[NN];
__device__ int            g_bsum[256];
__device__ int2           g_csr[NE];           // (edge_id, src_row) bucketed by dst
__device__ unsigned short g_WhT[DN * KTOT];    // combined weights^T [n=128][k=288], bf16 hi
__device__ unsigned short g_WlT[DN * KTOT];    // bf16 lo residual
__device__ float          g_v[DN];             // b1 @ W2b

// ---------------- init: weight folding (blocks 0..288) + zero g_deg (blocks 289+) ----
// Wc = [W2a ; W1a@W2b ; W1b@W2b], v = b1@W2b.  MUST precede k_fused (producer).
__global__ void k_init(const float* __restrict__ W1, const float* __restrict__ W2,
                       const float* __restrict__ b1) {
    if (blockIdx.x >= WCOMB_BLKS) {
        int i = (blockIdx.x - WCOMB_BLKS) * 256 + threadIdx.x;
        if (i < NN) g_deg[i] = 0;
        return;
    }
    int r = blockIdx.x;            // 0..288 (288 = bias-vector job)
    int j = threadIdx.x;           // only first 128 threads work
    if (j >= 128) return;
    if (r == KTOT) {
        float acc = 0.f;
        for (int k = 0; k < 128; k++) acc += b1[k] * W2[(128 + k) * 128 + j];
        g_v[j] = acc;
        return;
    }
    float w;
    if (r < 128) {
        w = W2[r * 128 + j];
    } else {
        float acc = 0.f;
        const float* w1r = W1 + (r - 128) * 128;   // rows 0..159 of W1
        for (int k = 0; k < 128; k++) acc += w1r[k] * W2[(128 + k) * 128 + j];
        w = acc;
    }
    __nv_bfloat16 hi = __float2bfloat16(w);
    __nv_bfloat16 lo = __float2bfloat16(w - __bfloat162float(hi));
    g_WhT[j * KTOT + r] = __bfloat16_as_ushort(hi);   // transposed: [n][k]
    g_WlT[j * KTOT + r] = __bfloat16_as_ushort(lo);
}

// ---------------- CSR build (edge_index is INT32: JAX x64 disabled) ----------------
__global__ void k_count(const int* __restrict__ ei) {
    int e = blockIdx.x * 256 + threadIdx.x;
    if (e < NE) atomicAdd(&g_deg[ei[NE + e]], 1);
}

__global__ void k_scan1() {
    __shared__ int s[1024];
    int t = threadIdx.x;
    int gid = blockIdx.x * 1024 + t;
    int v = (gid < NN) ? g_deg[gid] : 0;
    s[t] = v;
    __syncthreads();
    for (int d = 1; d < 1024; d <<= 1) {
        int u = (t >= d) ? s[t - d] : 0;
        __syncthreads();
        s[t] += u;
        __syncthreads();
    }
    if (gid < NN) g_off[gid] = s[t] - v;          // exclusive within block
    if (t == 1023) g_bsum[blockIdx.x] = s[1023];  // block total
}

// scan2 (block-sum prefix) merged into scan3: every block redundantly scans the
// 196 block sums in smem (cheap), then applies its single needed prefix.
__global__ void k_scan23() {
    __shared__ int s[256];
    __shared__ int pre;
    int t = threadIdx.x;
    int v = (t < NBLK1) ? g_bsum[t] : 0;
    s[t] = v;
    __syncthreads();
    for (int d = 1; d < 256; d <<= 1) {
        int u = (t >= d) ? s[t - d] : 0;
        __syncthreads();
        s[t] += u;
        __syncthreads();
    }
    int b = blockIdx.x >> 2;       // 256-thread block spans one 1024-aligned slice
    if (t == b) pre = s[t] - v;    // exclusive prefix for scan1-block b
    __syncthreads();
    int i = blockIdx.x * 256 + t;
    if (i < NN) {
        int o = g_off[i] + pre;
        g_off[i]    = o;
        g_cursor[i] = o;
    }
}

__global__ void k_scatter(const int* __restrict__ ei) {
    int e = blockIdx.x * 256 + threadIdx.x;
    if (e < NE) {
        int col = ei[NE + e];
        int row = ei[e];
        int p = atomicAdd(&g_cursor[col], 1);
        g_csr[p] = make_int2(e, row);
    }
}

// ---------------- fused aggregate + GEMM ----------------
// Phase 1: per block of 64 dst nodes, aggregate S1 (128f) | S2 (32f) into smem fp32
//          (register accumulate per node -> single STS, no smem RMW chains).
// Phase 2: out = [x | S1 | S2] @ Wc + deg*v + b2 via 3-pass bf16-split HMMA,
//          A chunks c<8 from global x, c>=8 from the smem agg buffer.
#define AS 12        // u32 stride; {0..7}*12 mod 32 distinct -> conflict-free frags
#define AGGS 44      // agg row stride in float4; 44*4=176 floats, 176%32=16 ->
                     // 8-lane f4 phases hit banks {0,4,..,28}: conflict-free

#define SM_AGG_BYTES (GBM * AGGS * 16)            // 45056
#define SM_AH   (SM_AGG_BYTES)                    // [64][12] u32
#define SM_AL   (SM_AH + GBM * AS * 4)            // +3072
#define SM_BH   (SM_AL + GBM * AS * 4)            // +3072
#define SM_BL   (SM_BH + DN * AS * 4)             // +6144
#define SM_TOT  (SM_BL + DN * AS * 4)             // 63488 total

#define MMA_BF16(d, a, bv0, bv1)                                            \
    asm volatile("mma.sync.aligned.m16n8k16.row.col.f32.bf16.bf16.f32 "     \
                 "{%0,%1,%2,%3}, {%4,%5,%6,%7}, {%8,%9}, {%0,%1,%2,%3};\n"  \
                 : "+f"(d[0]), "+f"(d[1]), "+f"(d[2]), "+f"(d[3])           \
                 : "r"(a[0]), "r"(a[1]), "r"(a[2]), "r"(a[3]),              \
                   "r"(bv0), "r"(bv1))

__device__ __forceinline__ unsigned pack_bf16x2(float a, float b) {
    __nv_bfloat162 h = __floats2bfloat162_rn(a, b);   // a -> low, b -> high
    return *reinterpret_cast<unsigned*>(&h);
}

__global__ __launch_bounds__(256) void k_fused(const float4* __restrict__ x4,
                                               const float4* __restrict__ ea4,
                                               const float* __restrict__ b2,
                                               float* __restrict__ out) {
    extern __shared__ unsigned char dsm[];
    float4*   agg = reinterpret_cast<float4*>(dsm);          // [GBM][AGGS]
    unsigned* Ah  = reinterpret_cast<unsigned*>(dsm + SM_AH);
    unsigned* Al  = reinterpret_cast<unsigned*>(dsm + SM_AL);
    unsigned* Bh  = reinterpret_cast<unsigned*>(dsm + SM_BH);
    unsigned* Bl  = reinterpret_cast<unsigned*>(dsm + SM_BL);

    int tid  = threadIdx.x;
    int lane = tid & 31;
    int warp = tid >> 5;
    int n0   = blockIdx.x * GBM;

    // ---- Phase 1: aggregation (warp handles 8 nodes) ----
    for (int j = 0; j < 8; j++) {
        int nl   = warp * 8 + j;
        int node = n0 + nl;
        int start = g_off[node];
        int cnt   = g_deg[node];
        float ax = 0.f, ay = 0.f, az = 0.f, aw = 0.f;
        float ex = 0.f, ey = 0.f, ez = 0.f, ew = 0.f;
        for (int e = 0; e < cnt; e++) {
            int2 c = g_csr[start + e];                       // broadcast load
            float4 xv = x4[(long long)c.y * 32 + lane];
            ax += xv.x; ay += xv.y; az += xv.z; aw += xv.w;
            if (lane < 8) {
                float4 ev = ea4[(long long)c.x * 8 + lane];
                ex += ev.x; ey += ev.y; ez += ev.z; ew += ev.w;
            }
        }
        agg[nl * AGGS + lane] = make_float4(ax, ay, az, aw); // S1: f4 0..31
        if (lane < 8)
            agg[nl * AGGS + 32 + lane] = make_float4(ex, ey, ez, ew); // S2: f4 32..39
    }
    __syncthreads();

    // ---- Phase 2: GEMM ----
    int wm = warp & 1;      // 2 warps along M (32 rows each)
    int wn = warp >> 1;     // 4 warps along N (32 cols each)

    float acc[2][4][4];
#pragma unroll
    for (int a = 0; a < 2; a++)
#pragma unroll
        for (int b = 0; b < 4; b++)
#pragma unroll
            for (int q = 0; q < 4; q++) acc[a][b][q] = 0.f;

    for (int c = 0; c < 18; c++) {     // 18 chunks of K=16 over KTOT=288
        __syncthreads();
        // A tile: 64 rows x 16 k; one float4 per thread (256 = 64*4)
        {
            int row = tid >> 2, f4 = tid & 3;
            float4 v;
            if (c < 8)       v = x4[(long long)(n0 + row) * 32 + c * 4 + f4];
            else if (c < 16) v = agg[row * AGGS + (c - 8) * 4 + f4];
            else             v = agg[row * AGGS + 32 + (c - 16) * 4 + f4];
            unsigned h0 = pack_bf16x2(v.x, v.y);
            unsigned h1 = pack_bf16x2(v.z, v.w);
            float rx = v.x - __bfloat162float(__ushort_as_bfloat16((unsigned short)(h0 & 0xFFFF)));
            float ry = v.y - __bfloat162float(__ushort_as_bfloat16((unsigned short)(h0 >> 16)));
            float rz = v.z - __bfloat162float(__ushort_as_bfloat16((unsigned short)(h1 & 0xFFFF)));
            float rw = v.w - __bfloat162float(__ushort_as_bfloat16((unsigned short)(h1 >> 16)));
            int base = row * AS + f4 * 2;
            Ah[base + 0] = h0;
            Ah[base + 1] = h1;
            Al[base + 0] = pack_bf16x2(rx, ry);
            Al[base + 1] = pack_bf16x2(rz, rw);
        }
        // B tile: 128 n x 16 k, straight copy of pre-split packed weights
        {
            const uint4* wh4 = reinterpret_cast<const uint4*>(g_WhT);
            const uint4* wl4 = reinterpret_cast<const uint4*>(g_WlT);
            int n = tid >> 1;                   // 0..127
            int q = tid & 1;                    // 0..1 (kk quad)
            uint4 vh = wh4[n * (NKK / 4) + c * 2 + q];
            uint4 vl = wl4[n * (NKK / 4) + c * 2 + q];
            int base = n * AS + q * 4;
            Bh[base + 0] = vh.x; Bh[base + 1] = vh.y; Bh[base + 2] = vh.z; Bh[base + 3] = vh.w;
            Bl[base + 0] = vl.x; Bl[base + 1] = vl.y; Bl[base + 2] = vl.z; Bl[base + 3] = vl.w;
        }
        __syncthreads();

        unsigned ah[2][4], al[2][4];
#pragma unroll
        for (int tm = 0; tm < 2; tm++) {
            int r  = wm * 32 + tm * 16 + (lane >> 2);
            int kk = lane & 3;
            ah[tm][0] = Ah[r * AS + kk];
            ah[tm][1] = Ah[(r + 8) * AS + kk];
            ah[tm][2] = Ah[r * AS + kk + 4];
            ah[tm][3] = Ah[(r + 8) * AS + kk + 4];
            al[tm][0] = Al[r * AS + kk];
            al[tm][1] = Al[(r + 8) * AS + kk];
            al[tm][2] = Al[r * AS + kk + 4];
            al[tm][3] = Al[(r + 8) * AS + kk + 4];
        }
#pragma unroll
        for (int tn = 0; tn < 4; tn++) {
            int col = wn * 32 + tn * 8 + (lane >> 2);
            int kk  = lane & 3;
            unsigned bh0 = Bh[col * AS + kk];
            unsigned bh1 = Bh[col * AS + kk + 4];
            unsigned bl0 = Bl[col * AS + kk];
            unsigned bl1 = Bl[col * AS + kk + 4];
#pragma unroll
            for (int tm = 0; tm < 2; tm++) {
                MMA_BF16(acc[tm][tn], ah[tm], bh0, bh1);   // hi*hi
                MMA_BF16(acc[tm][tn], ah[tm], bl0, bl1);   // hi*lo
                MMA_BF16(acc[tm][tn], al[tm], bh0, bh1);   // lo*hi
            }
        }
    }
    // epilogue: + deg*v + b2  (no bounds checks: 3125*64 == NN exactly)
#pragma unroll
    for (int tm = 0; tm < 2; tm++) {
        int r0 = n0 + wm * 32 + tm * 16 + (lane >> 2);
        int r1 = r0 + 8;
        float d0 = (float)g_deg[r0];
        float d1 = (float)g_deg[r1];
#pragma unroll
        for (int tn = 0; tn < 4; tn++) {
            int cc = wn * 32 + tn * 8 + 2 * (lane & 3);
            float v0 = g_v[cc], v1 = g_v[cc + 1];
            float c0 = b2[cc],  c1 = b2[cc + 1];
            float2 o0 = make_float2(acc[tm][tn][0] + d0 * v0 + c0,
                                    acc[tm][tn][1] + d0 * v1 + c1);
            float2 o1 = make_float2(acc[tm][tn][2] + d1 * v0 + c0,
                                    acc[tm][tn][3] + d1 * v1 + c1);
            *reinterpret_cast<float2*>(out + (long long)r0 * 128 + cc) = o0;
            *reinterpret_cast<float2*>(out + (long long)r1 * 128 + cc) = o1;
        }
    }
}

// ---------------- launch: 6 kernels, k_fused is launch #6 ----------------
extern "C" void kernel_launch(void* const* d_in, const int* in_sizes, int n_in,
                              void* d_out, int out_size) {
    const float* x  = (const float*)d_in[0];
    const int*   ei = (const int*)d_in[1];     // int32! JAX x64 disabled
    const float* ea = (const float*)d_in[2];
    // d_in[3]=u, d_in[4]=batch: unused by the reference computation
    const float* W1 = (const float*)d_in[5];
    const float* b1 = (const float*)d_in[6];
    const float* W2 = (const float*)d_in[7];
    const float* b2 = (const float*)d_in[8];
    float*       out = (float*)d_out;

    (void)in_sizes; (void)n_in; (void)out_size;

    cudaFuncSetAttribute(k_fused, cudaFuncAttributeMaxDynamicSharedMemorySize, SM_TOT);

    k_init<<<WCOMB_BLKS + ZERO_BLKS, 256>>>(W1, W2, b1);   // weights BEFORE fused
    k_count<<<(NE + 255) / 256, 256>>>(ei);
    k_scan1<<<NBLK1, 1024>>>();
    k_scan23<<<(NN + 255) / 256, 256>>>();
    k_scatter<<<(NE + 255) / 256, 256>>>(ei);
    k_fused<<<NGRID, 256, SM_TOT>>>((const float4*)x, (const float4*)ea, b2, out);
}